// round 5
// baseline (speedup 1.0000x reference)
#include <cuda_runtime.h>
#include <cuda_bf16.h>
#include <math.h>

#define B_   4
#define S_   4096
#define D_   768
#define H_   12
#define DH_  64
#define BS_  64
#define L_   2
#define R_   3
#define FF_  3072
#define NB_  64
#define NSEL_ 8
#define D3_  2304
#define M_   (B_*S_)

// ---------------- scratch (static device globals; no allocation) ----------------
__device__ float g_h   [(size_t)M_*D_];    // hidden state (fp32, for residual/LN)
__device__ float g_qkv [(size_t)M_*D3_];   // qkv projection (fp32, attention input)
__device__ float g_tmp [(size_t)M_*D_];    // projection output (fp32, residual)
__device__ __nv_bfloat16 g_hb   [(size_t)M_*D_];   // bf16 copy of h (GEMM A input)
__device__ __nv_bfloat16 g_attnb[(size_t)M_*D_];   // attention out (bf16, Wo A input)
__device__ __nv_bfloat16 g_ffb  [(size_t)M_*FF_];  // gelu(ff1) (bf16, FF2 A input)
// transposed bf16 weights: [N,K] layout
__device__ __nv_bfloat16 g_wqkvT[(size_t)L_*D3_*D_];
__device__ __nv_bfloat16 g_woT  [(size_t)L_*D_*D_];
__device__ __nv_bfloat16 g_wff1T[(size_t)L_*FF_*D_];
__device__ __nv_bfloat16 g_wff2T[(size_t)L_*D_*FF_];

__device__ __forceinline__ const __nv_bfloat16* bbuf_sel(int s) {
    switch (s) {
        case 0: return g_hb;
        case 1: return g_attnb;
        default: return g_ffb;
    }
}

__device__ __forceinline__ float gelu_f(float x) {
    float x3 = x * x * x;
    return 0.5f * x * (1.0f + tanhf(0.7978845608028654f * (x + 0.044715f * x3)));
}

// ---------------- asm helpers ----------------
__device__ __forceinline__ void cp16(unsigned dst, const void* src) {
    asm volatile("cp.async.cg.shared.global [%0], [%1], 16;" :: "r"(dst), "l"(src));
}
__device__ __forceinline__ void cp_commit() {
    asm volatile("cp.async.commit_group;");
}
__device__ __forceinline__ void ldmx4(unsigned r[4], unsigned addr) {
    asm volatile("ldmatrix.sync.aligned.m8n8.x4.shared.b16 {%0,%1,%2,%3}, [%4];"
                 : "=r"(r[0]), "=r"(r[1]), "=r"(r[2]), "=r"(r[3]) : "r"(addr));
}
__device__ __forceinline__ void mma_bf16(float c[4], const unsigned a[4],
                                         unsigned b0, unsigned b1) {
    asm volatile(
        "mma.sync.aligned.m16n8k16.row.col.f32.bf16.bf16.f32 "
        "{%0,%1,%2,%3}, {%4,%5,%6,%7}, {%8,%9}, {%0,%1,%2,%3};"
        : "+f"(c[0]), "+f"(c[1]), "+f"(c[2]), "+f"(c[3])
        : "r"(a[0]), "r"(a[1]), "r"(a[2]), "r"(a[3]), "r"(b0), "r"(b1));
}

// ---------------- weight convert+transpose: Wt[n][k] = bf16(W[k][n]) -----------
__global__ void __launch_bounds__(256) wconv_kernel(
    const float* __restrict__ W, __nv_bfloat16* __restrict__ Wt, int K, int N)
{
    __shared__ float tile[32][33];
    int n0 = blockIdx.x * 32, k0 = blockIdx.y * 32;
    int tx = threadIdx.x & 31, ty = threadIdx.x >> 5;  // 32 x 8
#pragma unroll
    for (int i = 0; i < 32; i += 8)
        tile[ty + i][tx] = W[(size_t)(k0 + ty + i) * N + n0 + tx];
    __syncthreads();
#pragma unroll
    for (int i = 0; i < 32; i += 8)
        Wt[(size_t)(n0 + ty + i) * K + k0 + tx] = __float2bfloat16(tile[tx][ty + i]);
}

// ---------------- bf16 tensor-core GEMM: C = act(A @ Bt^T + bias) --------------
// A: bf16 [M,K] row-major (scratch absel), Bt: bf16 [N,K] row-major (transposed W),
// out: fp32 (fsel) and/or bf16 (bsel). Tile 128x128x32, 256 thr, warp tile 64x32.
#define BM 128
#define BN 128
#define BK 32
#define LDS_ 40   // BK + 8 pad (80B row stride: 16B-aligned, ldmatrix conflict-free)

__global__ void __launch_bounds__(256) bf16_gemm_kernel(
    int absel, const __nv_bfloat16* __restrict__ Bt, const float* __restrict__ bias,
    int fsel, int bsel, int M, int N, int K, int act)
{
    const __nv_bfloat16* __restrict__ A = bbuf_sel(absel);
    float* Cf = (fsel == 0) ? g_qkv : ((fsel == 1) ? g_tmp : nullptr);
    __nv_bfloat16* Cb = (bsel == 0) ? g_ffb : nullptr;

    __shared__ __align__(16) __nv_bfloat16 As[2][BM * LDS_];
    __shared__ __align__(16) __nv_bfloat16 Bs[2][BN * LDS_];

    int tid = threadIdx.x, lane = tid & 31, warp = tid >> 5;
    int wm = (warp >> 2) * 64, wn = (warp & 3) * 32;
    int rowBase = blockIdx.y * BM, colBase = blockIdx.x * BN;

    // cp.async mapping: thread -> (row = tid>>2 [+64], k-chunk = (tid&3)*8)
    int lrow = tid >> 2;
    int lkc = (tid & 3) * 8;
    const __nv_bfloat16* Ag = A + (size_t)(rowBase + lrow) * K + lkc;
    const __nv_bfloat16* Bg = Bt + (size_t)(colBase + lrow) * K + lkc;

    unsigned sA[2][2], sB[2][2];
#pragma unroll
    for (int bf = 0; bf < 2; bf++) {
#pragma unroll
        for (int h = 0; h < 2; h++) {
            sA[bf][h] = (unsigned)__cvta_generic_to_shared(&As[bf][(lrow + h * 64) * LDS_ + lkc]);
            sB[bf][h] = (unsigned)__cvta_generic_to_shared(&Bs[bf][(lrow + h * 64) * LDS_ + lkc]);
        }
    }

    float c[4][4][4];
#pragma unroll
    for (int i = 0; i < 4; i++)
#pragma unroll
        for (int j = 0; j < 4; j++)
#pragma unroll
            for (int r = 0; r < 4; r++) c[i][j][r] = 0.0f;

    // ldmatrix per-lane addressing: row = base + (lane&15), col = (lane>>4)*8
    int fr = lane & 15;
    int fc = (lane >> 4) * 8;
    unsigned aB[2], bB[2];
#pragma unroll
    for (int bf = 0; bf < 2; bf++) {
        aB[bf] = (unsigned)__cvta_generic_to_shared(&As[bf][(wm + fr) * LDS_ + fc]);
        bB[bf] = (unsigned)__cvta_generic_to_shared(&Bs[bf][(wn + fr) * LDS_ + fc]);
    }

    int nIter = K / BK;

    // prefetch stage 0
    cp16(sA[0][0], Ag);
    cp16(sA[0][1], Ag + (size_t)64 * K);
    cp16(sB[0][0], Bg);
    cp16(sB[0][1], Bg + (size_t)64 * K);
    cp_commit();

    for (int it = 0; it < nIter; it++) {
        int cur = it & 1;
        if (it + 1 < nIter) {
            int nxt = cur ^ 1;
            const __nv_bfloat16* ap = Ag + (size_t)(it + 1) * BK;
            const __nv_bfloat16* bp = Bg + (size_t)(it + 1) * BK;
            cp16(sA[nxt][0], ap);
            cp16(sA[nxt][1], ap + (size_t)64 * K);
            cp16(sB[nxt][0], bp);
            cp16(sB[nxt][1], bp + (size_t)64 * K);
            cp_commit();
            asm volatile("cp.async.wait_group 1;");
        } else {
            asm volatile("cp.async.wait_group 0;");
        }
        __syncthreads();

#pragma unroll
        for (int ks = 0; ks < BK; ks += 16) {
            unsigned a[4][4];
#pragma unroll
            for (int mf = 0; mf < 4; mf++)
                ldmx4(a[mf], aB[cur] + (unsigned)((mf * 16 * LDS_ + ks) * 2));
            unsigned bf0[4], bf1[4];
            ldmx4(bf0, bB[cur] + (unsigned)(ks * 2));
            ldmx4(bf1, bB[cur] + (unsigned)((16 * LDS_ + ks) * 2));
            // nf0: {bf0[0],bf0[2]}  nf1: {bf0[1],bf0[3]}  nf2/3: bf1 same
#pragma unroll
            for (int mf = 0; mf < 4; mf++) {
                mma_bf16(c[mf][0], a[mf], bf0[0], bf0[2]);
                mma_bf16(c[mf][1], a[mf], bf0[1], bf0[3]);
                mma_bf16(c[mf][2], a[mf], bf1[0], bf1[2]);
                mma_bf16(c[mf][3], a[mf], bf1[1], bf1[3]);
            }
        }
        __syncthreads();
    }

    // epilogue
#pragma unroll
    for (int mf = 0; mf < 4; mf++) {
        int row0 = rowBase + wm + mf * 16 + (lane >> 2);
#pragma unroll
        for (int nf = 0; nf < 4; nf++) {
            int col = colBase + wn + nf * 8 + (lane & 3) * 2;
            float b0 = bias[col], b1 = bias[col + 1];
            float v0 = c[mf][nf][0] + b0;
            float v1 = c[mf][nf][1] + b1;
            float v2 = c[mf][nf][2] + b0;
            float v3 = c[mf][nf][3] + b1;
            if (act == 1) { v0 = gelu_f(v0); v1 = gelu_f(v1); v2 = gelu_f(v2); v3 = gelu_f(v3); }
            if (Cf) {
                float* p0 = Cf + (size_t)row0 * N + col;
                float* p1 = Cf + (size_t)(row0 + 8) * N + col;
                p0[0] = v0; p0[1] = v1;
                p1[0] = v2; p1[1] = v3;
            }
            if (Cb) {
                __nv_bfloat162* q0 = (__nv_bfloat162*)(Cb + (size_t)row0 * N + col);
                __nv_bfloat162* q1 = (__nv_bfloat162*)(Cb + (size_t)(row0 + 8) * N + col);
                *q0 = __floats2bfloat162_rn(v0, v1);
                *q1 = __floats2bfloat162_rn(v2, v3);
            }
        }
    }
}

// ---------------- embedding + layernorm (writes f32 + bf16) ----------------
__global__ void __launch_bounds__(256) embed_ln_kernel(
    const int* __restrict__ ids, const float* __restrict__ emb,
    const float* __restrict__ pos, const float* __restrict__ gamma,
    const float* __restrict__ beta)
{
    int tok = blockIdx.x;
    int s = tok % S_;
    __shared__ float xs[D_];
    __shared__ float red[256];
    int t = threadIdx.x;

    int id = ids[tok];
    const float* er = emb + (size_t)id * D_;
    const float* pr = pos + (size_t)s * D_;

    float lsum = 0.0f;
    for (int d = t; d < D_; d += 256) {
        float v = er[d] + pr[d];
        xs[d] = v;
        lsum += v;
    }
    red[t] = lsum; __syncthreads();
    for (int st = 128; st > 0; st >>= 1) { if (t < st) red[t] += red[t + st]; __syncthreads(); }
    float mean = red[0] * (1.0f / D_);
    __syncthreads();

    float vs = 0.0f;
    for (int d = t; d < D_; d += 256) { float dv = xs[d] - mean; vs += dv * dv; }
    red[t] = vs; __syncthreads();
    for (int st = 128; st > 0; st >>= 1) { if (t < st) red[t] += red[t + st]; __syncthreads(); }
    float rinv = rsqrtf(red[0] * (1.0f / D_) + 1e-12f);
    __syncthreads();

    float* out = g_h + (size_t)tok * D_;
    __nv_bfloat16* outb = g_hb + (size_t)tok * D_;
    for (int d = t; d < D_; d += 256) {
        float v = (xs[d] - mean) * rinv * gamma[d] + beta[d];
        out[d] = v;
        outb[d] = __float2bfloat16(v);
    }
}

// ---------------- residual add + layernorm (g_h += g_tmp, LN; dual write) ------
__global__ void __launch_bounds__(256) resid_ln_kernel(
    const float* __restrict__ gamma, const float* __restrict__ beta)
{
    int tok = blockIdx.x;
    __shared__ float xs[D_];
    __shared__ float red[256];
    int t = threadIdx.x;

    const float* hr = g_h + (size_t)tok * D_;
    const float* tr = g_tmp + (size_t)tok * D_;

    float lsum = 0.0f;
    for (int d = t; d < D_; d += 256) {
        float v = hr[d] + tr[d];
        xs[d] = v;
        lsum += v;
    }
    red[t] = lsum; __syncthreads();
    for (int st = 128; st > 0; st >>= 1) { if (t < st) red[t] += red[t + st]; __syncthreads(); }
    float mean = red[0] * (1.0f / D_);
    __syncthreads();

    float vs = 0.0f;
    for (int d = t; d < D_; d += 256) { float dv = xs[d] - mean; vs += dv * dv; }
    red[t] = vs; __syncthreads();
    for (int st = 128; st > 0; st >>= 1) { if (t < st) red[t] += red[t + st]; __syncthreads(); }
    float rinv = rsqrtf(red[0] * (1.0f / D_) + 1e-12f);
    __syncthreads();

    float* out = g_h + (size_t)tok * D_;
    __nv_bfloat16* outb = g_hb + (size_t)tok * D_;
    for (int d = t; d < D_; d += 256) {
        float v = (xs[d] - mean) * rinv * gamma[d] + beta[d];
        out[d] = v;
        outb[d] = __float2bfloat16(v);
    }
}

// ---------------- block-sparse attention (256 thr: 64 rows x 4 dim-chunks) -----
__global__ void __launch_bounds__(256) attn_kernel(
    const int* __restrict__ mask, const int* __restrict__ rand_idx)
{
    __shared__ float Ks[BS_][DH_];
    __shared__ float Vs[BS_][DH_];
    __shared__ float scS[BS_][BS_ + 1];
    __shared__ float biasS[BS_];

    int nb = blockIdx.x, hh = blockIdx.y, b = blockIdx.z;
    int tid = threadIdx.x;
    int t = tid >> 2;      // query row
    int c = tid & 3;       // dim chunk (16 dims)

    int sel[NSEL_];
    sel[0] = 0;
    sel[1] = (nb + NB_ - 1) % NB_;
    sel[2] = nb;
    sel[3] = (nb + 1) % NB_;
    sel[4] = NB_ - 1;
    sel[5] = rand_idx[nb * R_ + 0];
    sel[6] = rand_idx[nb * R_ + 1];
    sel[7] = rand_idx[nb * R_ + 2];

    const float scale = 0.125f;
    float q[16], o[16];
    const float* qrow = g_qkv + (size_t)(b * S_ + nb * BS_ + t) * D3_ + hh * DH_ + c * 16;
#pragma unroll
    for (int d = 0; d < 16; d++) { q[d] = qrow[d] * scale; o[d] = 0.0f; }

    float mx = -1e30f, lsum = 0.0f;

    for (int sblk = 0; sblk < NSEL_; sblk++) {
        int kb = sel[sblk];
        size_t kbase = (size_t)(b * S_ + kb * BS_) * D3_ + D_ + hh * DH_;
        size_t vbase = kbase + D_;

        // load K and V tiles (256 threads, coalesced rows)
#pragma unroll
        for (int i = 0; i < 16; i++) {
            int idx = tid + i * 256;
            int r = idx >> 6, dc = idx & 63;
            Ks[r][dc] = g_qkv[kbase + (size_t)r * D3_ + dc];
            Vs[r][dc] = g_qkv[vbase + (size_t)r * D3_ + dc];
        }
        if (tid < BS_) biasS[tid] = (mask[b * S_ + kb * BS_ + tid] > 0) ? 0.0f : -1e9f;
        __syncthreads();

        float bm = -1e30f;
        for (int j = 0; j < BS_; j++) {
            const float4* kr = (const float4*)&Ks[j][c * 16];
            float4 k0 = kr[0], k1 = kr[1], k2 = kr[2], k3 = kr[3];
            float s = q[0]*k0.x + q[1]*k0.y + q[2]*k0.z + q[3]*k0.w
                    + q[4]*k1.x + q[5]*k1.y + q[6]*k1.z + q[7]*k1.w
                    + q[8]*k2.x + q[9]*k2.y + q[10]*k2.z + q[11]*k2.w
                    + q[12]*k3.x + q[13]*k3.y + q[14]*k3.z + q[15]*k3.w;
            s += __shfl_xor_sync(0xffffffffu, s, 1);
            s += __shfl_xor_sync(0xffffffffu, s, 2);
            s += biasS[j];
            if (c == 0) scS[j][t] = s;
            bm = fmaxf(bm, s);
        }
        __syncwarp();

        float mnew = fmaxf(mx, bm);
        float corr = __expf(mx - mnew);
        lsum *= corr;
#pragma unroll
        for (int d = 0; d < 16; d++) o[d] *= corr;

        for (int j = 0; j < BS_; j++) {
            float p = __expf(scS[j][t] - mnew);
            lsum += p;
            const float4* vr = (const float4*)&Vs[j][c * 16];
            float4 v0 = vr[0], v1 = vr[1], v2 = vr[2], v3 = vr[3];
            o[0] += p*v0.x;  o[1] += p*v0.y;  o[2] += p*v0.z;  o[3] += p*v0.w;
            o[4] += p*v1.x;  o[5] += p*v1.y;  o[6] += p*v1.z;  o[7] += p*v1.w;
            o[8] += p*v2.x;  o[9] += p*v2.y;  o[10] += p*v2.z; o[11] += p*v2.w;
            o[12] += p*v3.x; o[13] += p*v3.y; o[14] += p*v3.z; o[15] += p*v3.w;
        }
        mx = mnew;
        __syncthreads();
    }

    float inv = 1.0f / lsum;
    __nv_bfloat16* outp = g_attnb + (size_t)(b * S_ + nb * BS_ + t) * D_ + hh * DH_ + c * 16;
#pragma unroll
    for (int d = 0; d < 16; d += 2)
        *(__nv_bfloat162*)(outp + d) = __floats2bfloat162_rn(o[d] * inv, o[d + 1] * inv);
}

// ---------------- pooler + classifier + loss ----------------
__global__ void __launch_bounds__(256) head_kernel(
    const float* __restrict__ Wp, const float* __restrict__ bp,
    const float* __restrict__ Wc, const float* __restrict__ bc,
    const int* __restrict__ label, float* __restrict__ out, int out_size)
{
    __shared__ float pooled[B_][D_];
    int t = threadIdx.x;

    for (int b = 0; b < B_; b++) {
        const float* x = g_h + (size_t)b * S_ * D_;
        for (int j = t; j < D_; j += 256) {
            float acc = bp[j];
            for (int d = 0; d < D_; d++) acc += x[d] * Wp[(size_t)d * D_ + j];
            pooled[b][j] = tanhf(acc);
        }
    }
    __syncthreads();

    if (t == 0) {
        float loss = 0.0f;
        for (int b = 0; b < B_; b++) {
            float lg0 = bc[0], lg1 = bc[1];
            for (int j = 0; j < D_; j++) {
                float pv = pooled[b][j];
                lg0 += pv * Wc[j * 2 + 0];
                lg1 += pv * Wc[j * 2 + 1];
            }
            float m = fmaxf(lg0, lg1);
            float e0 = expf(lg0 - m), e1 = expf(lg1 - m);
            float sinv = 1.0f / (e0 + e1);
            float p0 = e0 * sinv, p1 = e1 * sinv;
            out[b * 2 + 0] = p0;
            out[b * 2 + 1] = p1;
            float mm = fmaxf(p0, p1);
            float z = logf(expf(p0 - mm) + expf(p1 - mm)) + mm;
            float lp = ((label[b] == 0) ? p0 : p1) - z;
            loss += -lp;
        }
        loss *= (1.0f / B_);
        if (out_size > B_ * 2) out[B_ * 2] = loss;
    }
}

// ---------------- launch ----------------
extern "C" void kernel_launch(void* const* d_in, const int* in_sizes, int n_in,
                              void* d_out, int out_size)
{
    const int*   input_ids = (const int*)d_in[0];
    const int*   attn_mask = (const int*)d_in[1];
    const int*   label     = (const int*)d_in[2];
    const int*   rand_idx  = (const int*)d_in[3];
    const float* emb   = (const float*)d_in[4];
    const float* pos   = (const float*)d_in[5];
    const float* lng   = (const float*)d_in[6];
    const float* lnb   = (const float*)d_in[7];
    const float* Wqkv  = (const float*)d_in[8];
    const float* bqkv  = (const float*)d_in[9];
    const float* Wo    = (const float*)d_in[10];
    const float* bo    = (const float*)d_in[11];
    const float* ln1g  = (const float*)d_in[12];
    const float* ln1b  = (const float*)d_in[13];
    const float* Wff1  = (const float*)d_in[14];
    const float* bff1  = (const float*)d_in[15];
    const float* Wff2  = (const float*)d_in[16];
    const float* bff2  = (const float*)d_in[17];
    const float* ln2g  = (const float*)d_in[18];
    const float* ln2b  = (const float*)d_in[19];
    const float* Wp    = (const float*)d_in[20];
    const float* bp    = (const float*)d_in[21];
    const float* Wc    = (const float*)d_in[22];
    const float* bc    = (const float*)d_in[23];

    __nv_bfloat16 *wqkvT, *woT, *wff1T, *wff2T;
    cudaGetSymbolAddress((void**)&wqkvT, g_wqkvT);
    cudaGetSymbolAddress((void**)&woT, g_woT);
    cudaGetSymbolAddress((void**)&wff1T, g_wff1T);
    cudaGetSymbolAddress((void**)&wff2T, g_wff2T);

    // convert+transpose weights (bf16 [N,K])
    for (int l = 0; l < L_; l++) {
        wconv_kernel<<<dim3(D3_ / 32, D_ / 32), 256>>>(
            Wqkv + (size_t)l * D_ * D3_, wqkvT + (size_t)l * D3_ * D_, D_, D3_);
        wconv_kernel<<<dim3(D_ / 32, D_ / 32), 256>>>(
            Wo + (size_t)l * D_ * D_, woT + (size_t)l * D_ * D_, D_, D_);
        wconv_kernel<<<dim3(FF_ / 32, D_ / 32), 256>>>(
            Wff1 + (size_t)l * D_ * FF_, wff1T + (size_t)l * FF_ * D_, D_, FF_);
        wconv_kernel<<<dim3(D_ / 32, FF_ / 32), 256>>>(
            Wff2 + (size_t)l * FF_ * D_, wff2T + (size_t)l * D_ * FF_, FF_, D_);
    }

    embed_ln_kernel<<<M_, 256>>>(input_ids, emb, pos, lng, lnb);

    for (int l = 0; l < L_; l++) {
        // qkv (fp32 out)
        bf16_gemm_kernel<<<dim3(D3_ / BN, M_ / BM), 256>>>(
            0, wqkvT + (size_t)l * D3_ * D_, bqkv + (size_t)l * D3_, 0, -1, M_, D3_, D_, 0);
        // sparse attention -> g_attnb (bf16)
        attn_kernel<<<dim3(NB_, H_, B_), 256>>>(attn_mask, rand_idx);
        // tmp = attn @ Wo (fp32 out)
        bf16_gemm_kernel<<<dim3(D_ / BN, M_ / BM), 256>>>(
            1, woT + (size_t)l * D_ * D_, bo + (size_t)l * D_, 1, -1, M_, D_, D_, 0);
        resid_ln_kernel<<<M_, 256>>>(ln1g + (size_t)l * D_, ln1b + (size_t)l * D_);
        // ffb = gelu(h @ Wff1) (bf16 out)
        bf16_gemm_kernel<<<dim3(FF_ / BN, M_ / BM), 256>>>(
            0, wff1T + (size_t)l * FF_ * D_, bff1 + (size_t)l * FF_, -1, 0, M_, FF_, D_, 1);
        // tmp = ffb @ Wff2 (fp32 out)
        bf16_gemm_kernel<<<dim3(D_ / BN, M_ / BM), 256>>>(
            2, wff2T + (size_t)l * D_ * FF_, bff2 + (size_t)l * D_, 1, -1, M_, D_, FF_, 0);
        resid_ln_kernel<<<M_, 256>>>(ln2g + (size_t)l * D_, ln2b + (size_t)l * D_);
    }

    head_kernel<<<1, 256>>>(Wp, bp, Wc, bc, label, (float*)d_out, out_size);
}